// round 15
// baseline (speedup 1.0000x reference)
#include <cuda_runtime.h>
#include <cuda_fp16.h>
#include <math.h>
#include <stdint.h>

// ---------------------------------------------------------------------------
// GSSM — HMMA fp16, round 15: single-launch tail.
// R14 state: main at ~94% of the legacy-HMMA ceiling; remaining pool is the
// aux/launch tail. This round: (1) heads fused into the persistent main
// kernel behind a device-wide release/acquire barrier (replay-safe
// generation counter; all CTAs resident so no deadlock); (2) xprep+wtsplit
// merged into one flat-dispatch launch. All arithmetic identical to R14.
//
// Inputs (metadata order):
//  0: x(32,2048,512) 1: W_theta(512,64) 2: b_theta(64)
//  3: W_lam(512,1024) 4: b_lam 5: W_delt 6: b_delt 7: W_inp 8: b_inp
//  9: W_par(128,2) 10: b_par(2) 11: W_add(1024,1) 12: b_add(1)
// Output: parity_logits (32,2) at [0,64), add_pred (32,1) at [64,96)
// ---------------------------------------------------------------------------

#define B_ 32
#define T_ 2048
#define DIN_ 512
#define M_ 1024
#define K_ 64

#define TB 128               // t rows per tile
#define MB 64                // m cols per tile
#define KC 32                // k per sub-chunk
#define NPAIR 8              // 16 sub-chunks = 8 pairs per tile
#define NTT2 (T_ / TB)       // 16 t-tiles per batch
#define NMB (M_ / MB)        // 16 m-tiles
#define NTILES (NMB * B_ * NTT2)   // 8192
#define NSEG 64              // xs reduction segments (TS = 32)

#define NTHREADS 512

// smem sub-stage layout (fp16, padded rows of 40 elems = 80 B):
//   A: [128 rows][40]  = 10240 B ; B: [3 w][64 rows][40] = 15360 B
#define A_ROW_B 80
#define STAGE_A 10240
#define STAGE_BYTES 25600
#define RING_BYTES (STAGE_BYTES * 4)         // 102400 (2 pair-slots)
#define EPI_OFF RING_BYTES
#define SRS 132                               // sraw stride in floats ([m][t])
#define SRAW_BYTES (64 * SRS * 4)             // 33792 per array
#define SMEM_BYTES (RING_BYTES + 3 * SRAW_BYTES + 4096)   // 207872

// ---- static device scratch (no allocation allowed) ------------------------
__device__ __half g_xh[(size_t)B_ * T_ * DIN_];
__device__ __half g_wh[3u * M_ * DIN_];    // [w][m][k] K-major, fp16
__device__ float g_A[B_ * NTT2 * M_];
__device__ float g_D[B_ * NTT2 * M_];
__device__ float g_xsp[NSEG * B_ * DIN_];  // fp32 partial sums of x over T segs
__device__ unsigned int g_done = 0;        // arrival counter (reset each run)
__device__ unsigned int g_release = 0;     // monotonic generation (replay-safe)

// ---- helpers ---------------------------------------------------------------
__device__ __forceinline__ uint32_t smem_u32(const void* p) {
    uint32_t a;
    asm("{ .reg .u64 t; cvta.to.shared.u64 t, %1; cvt.u32.u64 %0, t; }"
        : "=r"(a) : "l"(p));
    return a;
}

__device__ __forceinline__ void cp_async16(uint32_t dst, const void* src) {
    asm volatile("cp.async.cg.shared.global [%0], [%1], 16;"
                 :: "r"(dst), "l"(src) : "memory");
}

__device__ __forceinline__ void ldsm_x4(uint32_t* r, uint32_t addr) {
    asm volatile("ldmatrix.sync.aligned.m8n8.x4.shared.b16 {%0,%1,%2,%3}, [%4];"
                 : "=r"(r[0]), "=r"(r[1]), "=r"(r[2]), "=r"(r[3]) : "r"(addr));
}

__device__ __forceinline__ void mma16816(float* d, const uint32_t* a,
                                         const uint32_t* b) {
    asm volatile(
        "mma.sync.aligned.m16n8k16.row.col.f32.f16.f16.f32 "
        "{%0,%1,%2,%3}, {%4,%5,%6,%7}, {%8,%9}, {%0,%1,%2,%3};"
        : "+f"(d[0]), "+f"(d[1]), "+f"(d[2]), "+f"(d[3])
        : "r"(a[0]), "r"(a[1]), "r"(a[2]), "r"(a[3]), "r"(b[0]), "r"(b[1]));
}

// |z| <= ~4 here, so the unstable form is safe
__device__ __forceinline__ float softplus_fast(float z) {
    return __logf(1.0f + __expf(z));
}

// ---------------------------------------------------------------------------
// Prep (merged): blocks [0, B_*NSEG): x -> fp16 + fp32 partial sums;
// blocks [B_*NSEG, +1536): W transpose to fp16. 128 threads.
// ---------------------------------------------------------------------------
__global__ void prep_kernel(const float* __restrict__ x,
                            const float* __restrict__ Wl,
                            const float* __restrict__ Wd,
                            const float* __restrict__ Wi) {
    __shared__ float tile[32][33];
    const int bid = blockIdx.x;
    const int tid = threadIdx.x;
    if (bid < B_ * NSEG) {
        const int b = bid >> 6;       // NSEG = 64
        const int seg = bid & 63;
        const int d0 = tid * 4;
        const int TS = T_ / NSEG;     // 32
        const float* xp = x + ((size_t)b * T_ + (size_t)seg * TS) * DIN_ + d0;
        __half* hp = g_xh + ((size_t)b * T_ + (size_t)seg * TS) * DIN_ + d0;
        float s0 = 0.f, s1 = 0.f, s2 = 0.f, s3 = 0.f;
#pragma unroll 8
        for (int t = 0; t < TS; ++t) {
            float4 v = *(const float4*)(xp + (size_t)t * DIN_);
            s0 += v.x; s1 += v.y; s2 += v.z; s3 += v.w;
            __align__(8) __half h[4] = {__float2half(v.x), __float2half(v.y),
                                        __float2half(v.z), __float2half(v.w)};
            *(uint2*)(hp + (size_t)t * DIN_) = *(const uint2*)h;
        }
        float4 outv = make_float4(s0, s1, s2, s3);
        *(float4*)&g_xsp[((size_t)seg * B_ + b) * DIN_ + d0] = outv;
    } else {
        const int idx = bid - B_ * NSEG;       // 0..1535
        const int w = idx >> 9;                // 0..2
        const int r2 = idx & 511;
        const float* W = (w == 0) ? Wl : ((w == 1) ? Wd : Wi);
        const int m0 = (r2 >> 4) * 32;
        const int k0 = (r2 & 15) * 32;
        const int tx = tid & 31;
        const int ty = tid >> 5;               // 0..3
#pragma unroll
        for (int r = 0; r < 8; ++r)
            tile[ty + 4 * r][tx] = W[(size_t)(k0 + ty + 4 * r) * M_ + m0 + tx];
        __syncthreads();
#pragma unroll
        for (int r = 0; r < 8; ++r) {
            int m = ty + 4 * r;
            int k = tx;
            size_t o = ((size_t)w * M_ + m0 + m) * DIN_ + k0 + k;
            g_wh[o] = __float2half(tile[k][m]);
        }
    }
}

// ---------------------------------------------------------------------------
// Main persistent kernel: HMMA GEMM + hidden epilogue + fused heads.
// ---------------------------------------------------------------------------
__global__ void __launch_bounds__(NTHREADS, 1)
gssm_mma_kernel(const float* __restrict__ b_lam,
                const float* __restrict__ b_delt,
                const float* __restrict__ b_inp,
                const float* __restrict__ W_theta,
                const float* __restrict__ b_theta,
                const float* __restrict__ W_par,
                const float* __restrict__ b_par,
                const float* __restrict__ W_add,
                const float* __restrict__ b_add,
                float* __restrict__ out) {
    extern __shared__ __align__(128) char smem[];
    const uint32_t sb = smem_u32(smem);
    const int tid = threadIdx.x;
    const int lane = tid & 31;
    const int wid = tid >> 5;
    const int wt = wid & 3;        // t-quadrant: rows wt*32..+31
    const int wm = wid >> 2;       // m-sixteenth: cols wm*16..+15

    // read the release generation BEFORE any work (replay-safe barrier)
    const unsigned int gen = *(volatile unsigned int*)&g_release;

    // ---- per-thread constant load offsets ----------------------------------
    const size_t constA = (size_t)(tid >> 2) * DIN_ + (size_t)(tid & 3) * 8;
    const uint32_t dstA = sb + (tid >> 2) * A_ROW_B + (tid & 3) * 16;
    size_t constB[2];
    uint32_t dstB[2];
#pragma unroll
    for (int q = 0; q < 2; ++q) {
        int idx = q * NTHREADS + tid;
        int w = idx >> 8;
        int n = (idx >> 2) & 63;
        int v = idx & 3;
        if (w > 2) w = 2;
        constB[q] = ((size_t)w * M_ + n) * DIN_ + (size_t)v * 8;
        dstB[q] = sb + STAGE_A + w * 5120 + n * A_ROW_B + v * 16;
    }
    const bool b1_active = (tid < 256);

    // ---- hoisted ldmatrix row offsets --------------------------------------
    const int rsub = (lane & 7) + 8 * ((lane >> 3) & 1);
    const int ksub2 = 16 * (lane >> 4);
    uint32_t aRow[2];
#pragma unroll
    for (int ts = 0; ts < 2; ++ts)
        aRow[ts] = (uint32_t)((wt * 32 + ts * 16 + rsub) * A_ROW_B) + ksub2;
    const uint32_t bRow =
        (uint32_t)(STAGE_A + (wm * 16 + rsub) * A_ROW_B) + ksub2;

    auto issue_pair = [&](const __half* bA, const __half* bB, int lp, int slot) {
        const uint32_t so0 = (uint32_t)slot * (2 * STAGE_BYTES);
        const size_t ko0 = (size_t)(2 * lp) * KC;
#pragma unroll
        for (int c = 0; c < 2; ++c) {
            const uint32_t so = so0 + c * STAGE_BYTES;
            const size_t ko = ko0 + c * KC;
            cp_async16(dstA + so, bA + constA + ko);
            cp_async16(dstB[0] + so, bB + constB[0] + ko);
            if (b1_active) cp_async16(dstB[1] + so, bB + constB[1] + ko);
        }
        asm volatile("cp.async.commit_group;" ::: "memory");
    };

    float acc[3][2][2][4];

    auto compute = [&](int stg) {
        const uint32_t base = sb + stg * STAGE_BYTES;
#pragma unroll
        for (int kk = 0; kk < 2; ++kk) {
            const uint32_t kb = base + kk * 32;
            uint32_t ah[2][4];
#pragma unroll
            for (int ts = 0; ts < 2; ++ts)
                ldsm_x4(ah[ts], kb + aRow[ts]);
            uint32_t bf[3][2][2];
#pragma unroll
            for (int w = 0; w < 3; ++w) {
                uint32_t r4[4];
                ldsm_x4(r4, kb + w * 5120 + bRow);
                bf[w][0][0] = r4[0];
                bf[w][1][0] = r4[1];
                bf[w][0][1] = r4[2];
                bf[w][1][1] = r4[3];
            }
#pragma unroll
            for (int w = 0; w < 3; ++w)
#pragma unroll
                for (int ts = 0; ts < 2; ++ts)
#pragma unroll
                    for (int nt = 0; nt < 2; ++nt)
                        mma16816(acc[w][ts][nt], ah[ts], bf[w][nt]);
        }
    };

    // ---- epilogue smem: raw stash [m][t] stride SRS; in-place converted ----
    float* sraw_l = (float*)(smem + EPI_OFF);                  // -> alpha
    float* sraw_d = (float*)(smem + EPI_OFF + SRAW_BYTES);     // -> drive
    float* sraw_i = (float*)(smem + EPI_OFF + 2 * SRAW_BYTES);
    float* sAp = (float*)(smem + EPI_OFF + 3 * SRAW_BYTES);        // [8][64]
    float* sDp = (float*)(smem + EPI_OFF + 3 * SRAW_BYTES + 2048); // [8][64]

    float4 bl4, bd4, bi4;   // biases of the stashed (previous) tile

    auto stash_tile = [&](int m0) {
        bl4 = *(const float4*)&b_lam[m0 + wid * 4];
        bd4 = *(const float4*)&b_delt[m0 + wid * 4];
        bi4 = *(const float4*)&b_inp[m0 + wid * 4];
#pragma unroll
        for (int ts = 0; ts < 2; ++ts)
#pragma unroll
            for (int nt = 0; nt < 2; ++nt)
#pragma unroll
                for (int h = 0; h < 2; ++h)
#pragma unroll
                    for (int c = 0; c < 2; ++c) {
                        const int t = wt * 32 + ts * 16 + h * 8 + (lane >> 2);
                        const int m = wm * 16 + nt * 8 + 2 * (lane & 3) + c;
                        const int o = m * SRS + t;
                        sraw_l[o] = acc[0][ts][nt][h * 2 + c];
                        sraw_d[o] = acc[1][ts][nt][h * 2 + c];
                        sraw_i[o] = acc[2][ts][nt][h * 2 + c];
                    }
    };

    auto slice = [&](int sp) {
        const int t = sp * 32 + lane;
        const float* blf = (const float*)&bl4;
        const float* bdf = (const float*)&bd4;
        const float* bif = (const float*)&bi4;
#pragma unroll
        for (int j = 0; j < 4; ++j) {
            const int o = (wid * 4 + j) * SRS + t;
            float zl = sraw_l[o] + blf[j];
            float zd = sraw_d[o] + bdf[j];
            float zi = sraw_i[o] + bif[j];
            float lamv = softplus_fast(zl);
            float dlv = softplus_fast(zd);
            sraw_l[o] = __expf(-dlv * lamv);
            sraw_d[o] = dlv * zi;
        }
    };

    auto scan_p2 = [&]() {
        const int m = tid & 63;
        const int ty = tid >> 6;
        float A = 1.f, D = 0.f;
#pragma unroll
        for (int r = 0; r < 16; ++r) {
            const int o = m * SRS + ty * 16 + r;
            float a = sraw_l[o];
            D = a * D + sraw_d[o];
            A *= a;
        }
        sAp[ty * 64 + m] = A;
        sDp[ty * 64 + m] = D;
    };
    auto scan_p3 = [&](size_t o) {
        if (tid < 64) {
            float A = 1.f, D = 0.f;
#pragma unroll
            for (int r = 0; r < 8; ++r) {
                float a = sAp[r * 64 + tid];
                D = a * D + sDp[r * 64 + tid];
                A *= a;
            }
            g_A[o + tid] = A;
            g_D[o + tid] = D;
        }
    };

    const int GS = gridDim.x;
    const int g0 = blockIdx.x;

    const __half* curA = g_xh + (size_t)(g0 >> 4) * TB * DIN_;
    const __half* curB = g_wh + (size_t)(g0 & 15) * MB * DIN_;
    int sc = 0;
    issue_pair(curA, curB, 0, 0);

    int prev_valid = 0;
    size_t prev_o = 0;

#pragma unroll 1
    for (int g = g0; g < NTILES; g += GS) {
        const int gn = g + GS;
        const bool has_next = (gn < NTILES);
        const __half* nxtA =
            has_next ? g_xh + (size_t)(gn >> 4) * TB * DIN_ : curA;
        const __half* nxtB =
            has_next ? g_wh + (size_t)(gn & 15) * MB * DIN_ : curB;
        const int m0 = (g & 15) * MB;

#pragma unroll
        for (int w = 0; w < 3; ++w)
#pragma unroll
            for (int ts = 0; ts < 2; ++ts)
#pragma unroll
                for (int nt = 0; nt < 2; ++nt)
#pragma unroll
                    for (int f = 0; f < 4; ++f) acc[w][ts][nt][f] = 0.f;

#pragma unroll 1
        for (int p = 0; p < NPAIR; ++p) {
            __syncthreads();
            if (p < 7)
                issue_pair(curA, curB, p + 1, sc ^ 1);
            else if (has_next)
                issue_pair(nxtA, nxtB, 0, sc ^ 1);
            if (prev_valid) {
                if (p < 4) slice(p);
                else if (p == 4) scan_p2();
                else if (p == 5) scan_p3(prev_o);
            }
            if (p < 7 || has_next)
                asm volatile("cp.async.wait_group 1;" ::: "memory");
            else
                asm volatile("cp.async.wait_group 0;" ::: "memory");
            compute(sc * 2);
            compute(sc * 2 + 1);
            sc ^= 1;
        }

        stash_tile(m0);
        prev_valid = 1;
        prev_o = (size_t)(g >> 4) * M_ + m0;
        curA = nxtA;
        curB = nxtB;
    }
    // drain: final tile's epilogue
    __syncthreads();
    slice(0); slice(1); slice(2); slice(3);
    __syncthreads();
    scan_p2();
    __syncthreads();
    scan_p3(prev_o);

    // ---- device-wide release/acquire barrier --------------------------------
    __threadfence();
    __syncthreads();
    if (tid == 0) {
        unsigned int old = atomicAdd(&g_done, 1u);
        if (old == (unsigned int)GS - 1u) {
            g_done = 0;                    // safe: only last arriver writes
            __threadfence();
            atomicAdd(&g_release, 1u);     // monotonic across graph replays
        }
    }
    if (blockIdx.x >= 2 * B_) return;      // non-head CTAs done
    if (tid == 0) {
        while (*(volatile unsigned int*)&g_release == gen) __nanosleep(32);
    }
    __syncthreads();
    __threadfence();

    // ---- fused heads: unit = blockIdx.x in [0, 64) --------------------------
    const int hb = blockIdx.x >> 1;
    if ((blockIdx.x & 1) == 0) {
        // combine + add head for batch hb
        float v = 0.f;
#pragma unroll 1
        for (int mm = tid; mm < M_; mm += NTHREADS) {
            float s = 0.f;
#pragma unroll
            for (int tt = 0; tt < NTT2; ++tt) {
                size_t idx = ((size_t)(hb * NTT2 + tt)) * M_ + mm;
                s = g_A[idx] * s + g_D[idx];
            }
            v += s * W_add[mm];
        }
        float* red = (float*)smem;
        for (int off = 16; off > 0; off >>= 1)
            v += __shfl_down_sync(0xffffffffu, v, off);
        if (lane == 0) red[wid] = v;
        __syncthreads();
        if (tid < 16) {
            float w = red[tid];
            for (int off = 8; off > 0; off >>= 1)
                w += __shfl_down_sync(0xffffu, w, off);
            if (tid == 0) out[2 * B_ + hb] = w + b_add[0];
        }
    } else {
        // parity head for batch hb (512 threads)
        float* xs = (float*)smem;                 // [512]
        float* part = xs + DIN_;                  // [8][64]
        float* gf = part + 8 * K_;                // [128]
        {
            float s[8] = {0.f, 0.f, 0.f, 0.f, 0.f, 0.f, 0.f, 0.f};
#pragma unroll
            for (int seg = 0; seg < NSEG; seg += 8)
#pragma unroll
                for (int j = 0; j < 8; ++j)
                    s[j] += g_xsp[((size_t)(seg + j) * B_ + hb) * DIN_ + tid];
            xs[tid] = ((s[0] + s[1]) + (s[2] + s[3])) +
                      ((s[4] + s[5]) + (s[6] + s[7]));
        }
        __syncthreads();
        const int k = tid & 63;
        const int q = tid >> 6;
        float a0 = 0.f, a1 = 0.f, a2 = 0.f, a3 = 0.f;
        const int dbase = q * 64;
#pragma unroll 4
        for (int i = 0; i < 64; i += 4) {
            a0 = fmaf(xs[dbase + i + 0], W_theta[(dbase + i + 0) * K_ + k], a0);
            a1 = fmaf(xs[dbase + i + 1], W_theta[(dbase + i + 1) * K_ + k], a1);
            a2 = fmaf(xs[dbase + i + 2], W_theta[(dbase + i + 2) * K_ + k], a2);
            a3 = fmaf(xs[dbase + i + 3], W_theta[(dbase + i + 3) * K_ + k], a3);
        }
        part[q * K_ + k] = (a0 + a1) + (a2 + a3);
        __syncthreads();
        if (tid < K_) {
            double acc2 = 0.0;
#pragma unroll
            for (int r = 0; r < 8; ++r) acc2 += (double)part[r * K_ + tid];
            acc2 += (double)T_ * (double)b_theta[tid];
            double ang = 3.14159265358979323846 * acc2;
            double sn, cs;
            sincos(ang, &sn, &cs);
            gf[tid] = (float)cs;
            gf[K_ + tid] = (float)sn;
        }
        __syncthreads();
        if (tid < 2) {
            float l = b_par[tid];
            for (int j = 0; j < 2 * K_; ++j)
                l += gf[j] * W_par[j * 2 + tid];
            out[hb * 2 + tid] = l;
        }
    }
}

// ---------------------------------------------------------------------------
extern "C" void kernel_launch(void* const* d_in, const int* in_sizes, int n_in,
                              void* d_out, int out_size) {
    const float* x       = (const float*)d_in[0];
    const float* W_theta = (const float*)d_in[1];
    const float* b_theta = (const float*)d_in[2];
    const float* W_lam   = (const float*)d_in[3];
    const float* b_lam   = (const float*)d_in[4];
    const float* W_delt  = (const float*)d_in[5];
    const float* b_delt  = (const float*)d_in[6];
    const float* W_inp   = (const float*)d_in[7];
    const float* b_inp   = (const float*)d_in[8];
    const float* W_par   = (const float*)d_in[9];
    const float* b_par   = (const float*)d_in[10];
    const float* W_add   = (const float*)d_in[11];
    const float* b_add   = (const float*)d_in[12];
    float* out = (float*)d_out;

    static int nsm = 0;
    if (!nsm) {
        cudaFuncSetAttribute(gssm_mma_kernel,
                             cudaFuncAttributeMaxDynamicSharedMemorySize,
                             SMEM_BYTES);
        if (cudaDeviceGetAttribute(&nsm, cudaDevAttrMultiProcessorCount, 0)
                != cudaSuccess || nsm <= 0)
            nsm = 148;
        if (nsm > NTILES) nsm = NTILES;
        if (nsm < 2 * B_) nsm = 2 * B_;   // ensure all head units exist
    }

    // Prep (merged single launch)
    prep_kernel<<<B_ * NSEG + 1536, 128>>>(x, W_lam, W_delt, W_inp);

    // Main: GEMM + hidden epilogue + device barrier + fused heads
    gssm_mma_kernel<<<nsm, NTHREADS, SMEM_BYTES>>>(
        b_lam, b_delt, b_inp, W_theta, b_theta, W_par, b_par,
        W_add, b_add, out);
}

// round 16
// speedup vs baseline: 1.0003x; 1.0003x over previous
#include <cuda_runtime.h>
#include <cuda_fp16.h>
#include <math.h>
#include <stdint.h>

// ---------------------------------------------------------------------------
// GSSM — HMMA fp16, round 16.
// R15 post-mortem: fusing heads behind a device-wide barrier cost ~40us
// (straggler serialization + regs 101->120) for a 14.5us kernel — reverted.
// This round: R14 main (measured best) + merged prep launch (kept from R15)
// + heads with PREFETCHED combine loads (the 14.5us was 16 serial gmem loads
// in the scan chain; prefetching makes them MLP-16).
//
// Inputs (metadata order):
//  0: x(32,2048,512) 1: W_theta(512,64) 2: b_theta(64)
//  3: W_lam(512,1024) 4: b_lam 5: W_delt 6: b_delt 7: W_inp 8: b_inp
//  9: W_par(128,2) 10: b_par(2) 11: W_add(1024,1) 12: b_add(1)
// Output: parity_logits (32,2) at [0,64), add_pred (32,1) at [64,96)
// ---------------------------------------------------------------------------

#define B_ 32
#define T_ 2048
#define DIN_ 512
#define M_ 1024
#define K_ 64

#define TB 128               // t rows per tile
#define MB 64                // m cols per tile
#define KC 32                // k per sub-chunk
#define NPAIR 8              // 16 sub-chunks = 8 pairs per tile
#define NTT2 (T_ / TB)       // 16 t-tiles per batch
#define NMB (M_ / MB)        // 16 m-tiles
#define NTILES (NMB * B_ * NTT2)   // 8192
#define NSEG 64              // xs reduction segments (TS = 32)

#define NTHREADS 512

// smem sub-stage layout (fp16, padded rows of 40 elems = 80 B):
//   A: [128 rows][40]  = 10240 B ; B: [3 w][64 rows][40] = 15360 B
#define A_ROW_B 80
#define STAGE_A 10240
#define STAGE_BYTES 25600
#define RING_BYTES (STAGE_BYTES * 4)         // 102400 (2 pair-slots)
#define EPI_OFF RING_BYTES
#define SRS 132                               // sraw stride in floats ([m][t])
#define SRAW_BYTES (64 * SRS * 4)             // 33792 per array
#define SMEM_BYTES (RING_BYTES + 3 * SRAW_BYTES + 4096)   // 207872

// ---- static device scratch (no allocation allowed) ------------------------
__device__ __half g_xh[(size_t)B_ * T_ * DIN_];
__device__ __half g_wh[3u * M_ * DIN_];    // [w][m][k] K-major, fp16
__device__ float g_A[B_ * NTT2 * M_];
__device__ float g_D[B_ * NTT2 * M_];
__device__ float g_xsp[NSEG * B_ * DIN_];  // fp32 partial sums of x over T segs

// ---- helpers ---------------------------------------------------------------
__device__ __forceinline__ uint32_t smem_u32(const void* p) {
    uint32_t a;
    asm("{ .reg .u64 t; cvta.to.shared.u64 t, %1; cvt.u32.u64 %0, t; }"
        : "=r"(a) : "l"(p));
    return a;
}

__device__ __forceinline__ void cp_async16(uint32_t dst, const void* src) {
    asm volatile("cp.async.cg.shared.global [%0], [%1], 16;"
                 :: "r"(dst), "l"(src) : "memory");
}

__device__ __forceinline__ void ldsm_x4(uint32_t* r, uint32_t addr) {
    asm volatile("ldmatrix.sync.aligned.m8n8.x4.shared.b16 {%0,%1,%2,%3}, [%4];"
                 : "=r"(r[0]), "=r"(r[1]), "=r"(r[2]), "=r"(r[3]) : "r"(addr));
}

__device__ __forceinline__ void mma16816(float* d, const uint32_t* a,
                                         const uint32_t* b) {
    asm volatile(
        "mma.sync.aligned.m16n8k16.row.col.f32.f16.f16.f32 "
        "{%0,%1,%2,%3}, {%4,%5,%6,%7}, {%8,%9}, {%0,%1,%2,%3};"
        : "+f"(d[0]), "+f"(d[1]), "+f"(d[2]), "+f"(d[3])
        : "r"(a[0]), "r"(a[1]), "r"(a[2]), "r"(a[3]), "r"(b[0]), "r"(b[1]));
}

// |z| <= ~4 here, so the unstable form is safe
__device__ __forceinline__ float softplus_fast(float z) {
    return __logf(1.0f + __expf(z));
}

// ---------------------------------------------------------------------------
// Prep (merged): blocks [0, B_*NSEG): x -> fp16 + fp32 partial sums;
// blocks [B_*NSEG, +1536): W transpose to fp16. 128 threads.
// ---------------------------------------------------------------------------
__global__ void prep_kernel(const float* __restrict__ x,
                            const float* __restrict__ Wl,
                            const float* __restrict__ Wd,
                            const float* __restrict__ Wi) {
    __shared__ float tile[32][33];
    const int bid = blockIdx.x;
    const int tid = threadIdx.x;
    if (bid < B_ * NSEG) {
        const int b = bid >> 6;       // NSEG = 64
        const int seg = bid & 63;
        const int d0 = tid * 4;
        const int TS = T_ / NSEG;     // 32
        const float* xp = x + ((size_t)b * T_ + (size_t)seg * TS) * DIN_ + d0;
        __half* hp = g_xh + ((size_t)b * T_ + (size_t)seg * TS) * DIN_ + d0;
        float s0 = 0.f, s1 = 0.f, s2 = 0.f, s3 = 0.f;
#pragma unroll 8
        for (int t = 0; t < TS; ++t) {
            float4 v = *(const float4*)(xp + (size_t)t * DIN_);
            s0 += v.x; s1 += v.y; s2 += v.z; s3 += v.w;
            __align__(8) __half h[4] = {__float2half(v.x), __float2half(v.y),
                                        __float2half(v.z), __float2half(v.w)};
            *(uint2*)(hp + (size_t)t * DIN_) = *(const uint2*)h;
        }
        float4 outv = make_float4(s0, s1, s2, s3);
        *(float4*)&g_xsp[((size_t)seg * B_ + b) * DIN_ + d0] = outv;
    } else {
        const int idx = bid - B_ * NSEG;       // 0..1535
        const int w = idx >> 9;                // 0..2
        const int r2 = idx & 511;
        const float* W = (w == 0) ? Wl : ((w == 1) ? Wd : Wi);
        const int m0 = (r2 >> 4) * 32;
        const int k0 = (r2 & 15) * 32;
        const int tx = tid & 31;
        const int ty = tid >> 5;               // 0..3
#pragma unroll
        for (int r = 0; r < 8; ++r)
            tile[ty + 4 * r][tx] = W[(size_t)(k0 + ty + 4 * r) * M_ + m0 + tx];
        __syncthreads();
#pragma unroll
        for (int r = 0; r < 8; ++r) {
            int m = ty + 4 * r;
            int k = tx;
            size_t o = ((size_t)w * M_ + m0 + m) * DIN_ + k0 + k;
            g_wh[o] = __float2half(tile[k][m]);
        }
    }
}

// ---------------------------------------------------------------------------
// Main persistent kernel (R14 structure, measured best).
// ---------------------------------------------------------------------------
__global__ void __launch_bounds__(NTHREADS, 1)
gssm_mma_kernel(const float* __restrict__ b_lam,
                const float* __restrict__ b_delt,
                const float* __restrict__ b_inp) {
    extern __shared__ __align__(128) char smem[];
    const uint32_t sb = smem_u32(smem);
    const int tid = threadIdx.x;
    const int lane = tid & 31;
    const int wid = tid >> 5;
    const int wt = wid & 3;        // t-quadrant: rows wt*32..+31
    const int wm = wid >> 2;       // m-sixteenth: cols wm*16..+15

    // ---- per-thread constant load offsets ----------------------------------
    const size_t constA = (size_t)(tid >> 2) * DIN_ + (size_t)(tid & 3) * 8;
    const uint32_t dstA = sb + (tid >> 2) * A_ROW_B + (tid & 3) * 16;
    size_t constB[2];
    uint32_t dstB[2];
#pragma unroll
    for (int q = 0; q < 2; ++q) {
        int idx = q * NTHREADS + tid;
        int w = idx >> 8;
        int n = (idx >> 2) & 63;
        int v = idx & 3;
        if (w > 2) w = 2;
        constB[q] = ((size_t)w * M_ + n) * DIN_ + (size_t)v * 8;
        dstB[q] = sb + STAGE_A + w * 5120 + n * A_ROW_B + v * 16;
    }
    const bool b1_active = (tid < 256);

    // ---- hoisted ldmatrix row offsets --------------------------------------
    const int rsub = (lane & 7) + 8 * ((lane >> 3) & 1);
    const int ksub2 = 16 * (lane >> 4);
    uint32_t aRow[2];
#pragma unroll
    for (int ts = 0; ts < 2; ++ts)
        aRow[ts] = (uint32_t)((wt * 32 + ts * 16 + rsub) * A_ROW_B) + ksub2;
    const uint32_t bRow =
        (uint32_t)(STAGE_A + (wm * 16 + rsub) * A_ROW_B) + ksub2;

    auto issue_pair = [&](const __half* bA, const __half* bB, int lp, int slot) {
        const uint32_t so0 = (uint32_t)slot * (2 * STAGE_BYTES);
        const size_t ko0 = (size_t)(2 * lp) * KC;
#pragma unroll
        for (int c = 0; c < 2; ++c) {
            const uint32_t so = so0 + c * STAGE_BYTES;
            const size_t ko = ko0 + c * KC;
            cp_async16(dstA + so, bA + constA + ko);
            cp_async16(dstB[0] + so, bB + constB[0] + ko);
            if (b1_active) cp_async16(dstB[1] + so, bB + constB[1] + ko);
        }
        asm volatile("cp.async.commit_group;" ::: "memory");
    };

    float acc[3][2][2][4];

    auto compute = [&](int stg) {
        const uint32_t base = sb + stg * STAGE_BYTES;
#pragma unroll
        for (int kk = 0; kk < 2; ++kk) {
            const uint32_t kb = base + kk * 32;
            uint32_t ah[2][4];
#pragma unroll
            for (int ts = 0; ts < 2; ++ts)
                ldsm_x4(ah[ts], kb + aRow[ts]);
            uint32_t bf[3][2][2];
#pragma unroll
            for (int w = 0; w < 3; ++w) {
                uint32_t r4[4];
                ldsm_x4(r4, kb + w * 5120 + bRow);
                bf[w][0][0] = r4[0];
                bf[w][1][0] = r4[1];
                bf[w][0][1] = r4[2];
                bf[w][1][1] = r4[3];
            }
#pragma unroll
            for (int w = 0; w < 3; ++w)
#pragma unroll
                for (int ts = 0; ts < 2; ++ts)
#pragma unroll
                    for (int nt = 0; nt < 2; ++nt)
                        mma16816(acc[w][ts][nt], ah[ts], bf[w][nt]);
        }
    };

    // ---- epilogue smem: raw stash [m][t] stride SRS; in-place converted ----
    float* sraw_l = (float*)(smem + EPI_OFF);                  // -> alpha
    float* sraw_d = (float*)(smem + EPI_OFF + SRAW_BYTES);     // -> drive
    float* sraw_i = (float*)(smem + EPI_OFF + 2 * SRAW_BYTES);
    float* sAp = (float*)(smem + EPI_OFF + 3 * SRAW_BYTES);        // [8][64]
    float* sDp = (float*)(smem + EPI_OFF + 3 * SRAW_BYTES + 2048); // [8][64]

    float4 bl4, bd4, bi4;   // biases of the stashed (previous) tile

    auto stash_tile = [&](int m0) {
        bl4 = *(const float4*)&b_lam[m0 + wid * 4];
        bd4 = *(const float4*)&b_delt[m0 + wid * 4];
        bi4 = *(const float4*)&b_inp[m0 + wid * 4];
#pragma unroll
        for (int ts = 0; ts < 2; ++ts)
#pragma unroll
            for (int nt = 0; nt < 2; ++nt)
#pragma unroll
                for (int h = 0; h < 2; ++h)
#pragma unroll
                    for (int c = 0; c < 2; ++c) {
                        const int t = wt * 32 + ts * 16 + h * 8 + (lane >> 2);
                        const int m = wm * 16 + nt * 8 + 2 * (lane & 3) + c;
                        const int o = m * SRS + t;
                        sraw_l[o] = acc[0][ts][nt][h * 2 + c];
                        sraw_d[o] = acc[1][ts][nt][h * 2 + c];
                        sraw_i[o] = acc[2][ts][nt][h * 2 + c];
                    }
    };

    auto slice = [&](int sp) {
        const int t = sp * 32 + lane;
        const float* blf = (const float*)&bl4;
        const float* bdf = (const float*)&bd4;
        const float* bif = (const float*)&bi4;
#pragma unroll
        for (int j = 0; j < 4; ++j) {
            const int o = (wid * 4 + j) * SRS + t;
            float zl = sraw_l[o] + blf[j];
            float zd = sraw_d[o] + bdf[j];
            float zi = sraw_i[o] + bif[j];
            float lamv = softplus_fast(zl);
            float dlv = softplus_fast(zd);
            sraw_l[o] = __expf(-dlv * lamv);
            sraw_d[o] = dlv * zi;
        }
    };

    auto scan_p2 = [&]() {
        const int m = tid & 63;
        const int ty = tid >> 6;
        float A = 1.f, D = 0.f;
#pragma unroll
        for (int r = 0; r < 16; ++r) {
            const int o = m * SRS + ty * 16 + r;
            float a = sraw_l[o];
            D = a * D + sraw_d[o];
            A *= a;
        }
        sAp[ty * 64 + m] = A;
        sDp[ty * 64 + m] = D;
    };
    auto scan_p3 = [&](size_t o) {
        if (tid < 64) {
            float A = 1.f, D = 0.f;
#pragma unroll
            for (int r = 0; r < 8; ++r) {
                float a = sAp[r * 64 + tid];
                D = a * D + sDp[r * 64 + tid];
                A *= a;
            }
            g_A[o + tid] = A;
            g_D[o + tid] = D;
        }
    };

    const int GS = gridDim.x;
    int g0 = blockIdx.x;
    if (g0 >= NTILES) return;

    const __half* curA = g_xh + (size_t)(g0 >> 4) * TB * DIN_;
    const __half* curB = g_wh + (size_t)(g0 & 15) * MB * DIN_;
    int sc = 0;
    issue_pair(curA, curB, 0, 0);

    int prev_valid = 0;
    size_t prev_o = 0;

#pragma unroll 1
    for (int g = g0; g < NTILES; g += GS) {
        const int gn = g + GS;
        const bool has_next = (gn < NTILES);
        const __half* nxtA =
            has_next ? g_xh + (size_t)(gn >> 4) * TB * DIN_ : curA;
        const __half* nxtB =
            has_next ? g_wh + (size_t)(gn & 15) * MB * DIN_ : curB;
        const int m0 = (g & 15) * MB;

#pragma unroll
        for (int w = 0; w < 3; ++w)
#pragma unroll
            for (int ts = 0; ts < 2; ++ts)
#pragma unroll
                for (int nt = 0; nt < 2; ++nt)
#pragma unroll
                    for (int f = 0; f < 4; ++f) acc[w][ts][nt][f] = 0.f;

#pragma unroll 1
        for (int p = 0; p < NPAIR; ++p) {
            __syncthreads();
            if (p < 7)
                issue_pair(curA, curB, p + 1, sc ^ 1);
            else if (has_next)
                issue_pair(nxtA, nxtB, 0, sc ^ 1);
            // hidden epilogue of the previous tile (ordered by the syncs)
            if (prev_valid) {
                if (p < 4) slice(p);
                else if (p == 4) scan_p2();
                else if (p == 5) scan_p3(prev_o);
            }
            if (p < 7 || has_next)
                asm volatile("cp.async.wait_group 1;" ::: "memory");
            else
                asm volatile("cp.async.wait_group 0;" ::: "memory");
            compute(sc * 2);
            compute(sc * 2 + 1);
            sc ^= 1;
        }

        stash_tile(m0);
        prev_valid = 1;
        prev_o = (size_t)(g >> 4) * M_ + m0;
        curA = nxtA;
        curB = nxtB;
    }
    // drain: final tile's epilogue
    __syncthreads();
    slice(0); slice(1); slice(2); slice(3);
    __syncthreads();
    scan_p2();
    __syncthreads();
    scan_p3(prev_o);
}

// ---------------------------------------------------------------------------
// Heads kernel: grid (B_, 2) x 1024 threads.
//  y==0: combine with PREFETCHED A/D (MLP-16 loads, then register scan)
//  y==1: parity head (512 threads)
// ---------------------------------------------------------------------------
__global__ void heads_kernel(const float* __restrict__ W_theta,
                             const float* __restrict__ b_theta,
                             const float* __restrict__ W_par,
                             const float* __restrict__ b_par,
                             const float* __restrict__ W_add,
                             const float* __restrict__ b_add,
                             float* __restrict__ out) {
    const int b = blockIdx.x;
    const int tid = threadIdx.x;
    if (blockIdx.y == 0) {
        const int m = tid;
        float Av[NTT2], Dv[NTT2];
#pragma unroll
        for (int tt = 0; tt < NTT2; ++tt) {     // independent loads, MLP 16
            size_t idx = ((size_t)(b * NTT2 + tt)) * M_ + m;
            Av[tt] = g_A[idx];
            Dv[tt] = g_D[idx];
        }
        float s = 0.f;
#pragma unroll
        for (int tt = 0; tt < NTT2; ++tt)
            s = Av[tt] * s + Dv[tt];
        float v = s * W_add[m];
        __shared__ float red[32];
        for (int off = 16; off > 0; off >>= 1)
            v += __shfl_down_sync(0xffffffffu, v, off);
        if ((m & 31) == 0) red[m >> 5] = v;
        __syncthreads();
        if (m < 32) {
            float w = red[m];
            for (int off = 16; off > 0; off >>= 1)
                w += __shfl_down_sync(0xffffffffu, w, off);
            if (m == 0) out[2 * B_ + b] = w + b_add[0];
        }
    } else {
        if (tid >= DIN_) return;
        __shared__ float xs[DIN_];
        {
            float s[8] = {0.f, 0.f, 0.f, 0.f, 0.f, 0.f, 0.f, 0.f};
#pragma unroll
            for (int seg = 0; seg < NSEG; seg += 8)
#pragma unroll
                for (int j = 0; j < 8; ++j)
                    s[j] += g_xsp[((size_t)(seg + j) * B_ + b) * DIN_ + tid];
            xs[tid] = ((s[0] + s[1]) + (s[2] + s[3])) +
                      ((s[4] + s[5]) + (s[6] + s[7]));
        }
        __syncthreads();
        const int k = tid & 63;
        const int q = tid >> 6;
        float a0 = 0.f, a1 = 0.f, a2 = 0.f, a3 = 0.f;
        const int dbase = q * 64;
#pragma unroll 4
        for (int i = 0; i < 64; i += 4) {
            a0 = fmaf(xs[dbase + i + 0], W_theta[(dbase + i + 0) * K_ + k], a0);
            a1 = fmaf(xs[dbase + i + 1], W_theta[(dbase + i + 1) * K_ + k], a1);
            a2 = fmaf(xs[dbase + i + 2], W_theta[(dbase + i + 2) * K_ + k], a2);
            a3 = fmaf(xs[dbase + i + 3], W_theta[(dbase + i + 3) * K_ + k], a3);
        }
        __shared__ float part[8][K_];
        part[q][k] = (a0 + a1) + (a2 + a3);
        __syncthreads();
        __shared__ float gf[2 * K_];
        if (tid < K_) {
            double acc = 0.0;
#pragma unroll
            for (int r = 0; r < 8; ++r) acc += (double)part[r][tid];
            acc += (double)T_ * (double)b_theta[tid];
            double ang = 3.14159265358979323846 * acc;
            double sn, cs;
            sincos(ang, &sn, &cs);
            gf[tid] = (float)cs;
            gf[K_ + tid] = (float)sn;
        }
        __syncthreads();
        if (tid < 2) {
            float l = b_par[tid];
            for (int j = 0; j < 2 * K_; ++j)
                l += gf[j] * W_par[j * 2 + tid];
            out[b * 2 + tid] = l;
        }
    }
}

// ---------------------------------------------------------------------------
extern "C" void kernel_launch(void* const* d_in, const int* in_sizes, int n_in,
                              void* d_out, int out_size) {
    const float* x       = (const float*)d_in[0];
    const float* W_theta = (const float*)d_in[1];
    const float* b_theta = (const float*)d_in[2];
    const float* W_lam   = (const float*)d_in[3];
    const float* b_lam   = (const float*)d_in[4];
    const float* W_delt  = (const float*)d_in[5];
    const float* b_delt  = (const float*)d_in[6];
    const float* W_inp   = (const float*)d_in[7];
    const float* b_inp   = (const float*)d_in[8];
    const float* W_par   = (const float*)d_in[9];
    const float* b_par   = (const float*)d_in[10];
    const float* W_add   = (const float*)d_in[11];
    const float* b_add   = (const float*)d_in[12];
    float* out = (float*)d_out;

    static int nsm = 0;
    if (!nsm) {
        cudaFuncSetAttribute(gssm_mma_kernel,
                             cudaFuncAttributeMaxDynamicSharedMemorySize,
                             SMEM_BYTES);
        if (cudaDeviceGetAttribute(&nsm, cudaDevAttrMultiProcessorCount, 0)
                != cudaSuccess || nsm <= 0)
            nsm = 148;
        if (nsm > NTILES) nsm = NTILES;
    }

    // Prep (merged single launch)
    prep_kernel<<<B_ * NSEG + 1536, 128>>>(x, W_lam, W_delt, W_inp);

    // Main fused tensor-core GEMM + fully hidden epilogue (persistent)
    gssm_mma_kernel<<<nsm, NTHREADS, SMEM_BYTES>>>(b_lam, b_delt, b_inp);

    // Heads (combine + parity in one launch)
    heads_kernel<<<dim3(B_, 2), 1024>>>(W_theta, b_theta, W_par, b_par,
                                        W_add, b_add, out);
}